// round 16
// baseline (speedup 1.0000x reference)
#include <cuda_runtime.h>
#include <cuda_bf16.h>
#include <cstdint>

// SSL2d: per-channel sub-pixel bilinear shift with zero padding.
// x: [B=32, C=384, H=56, W=56] fp32, a,b: [C] fp32.
//
// R16: R13 structure (7 rows/thread, MLP=8, shuffle boundary, __stcs stores)
// + createpolicy.RANGE: first PIN_BYTES of x are L2::evict_last, the rest
// evict_first. x (154MB) > L2 (126MB) cyclically thrashes under any uniform
// policy; pinning a fixed 100MB subset converts that subset to steady L2 hits
// across graph replays while the remainder streams.

#define SSL_H 56
#define SSL_W 56
#define SSL_C 384
#define ROWS_PT 7                           // output rows per thread
#define NRG (SSL_H / ROWS_PT)               // 8 rowgroups
#define NTHREADS (NRG * 16)                 // 128

#define X_BYTES (32u * 384u * 56u * 56u * 4u)   // 154,140,672
#define PIN_BYTES (100u * 1024u * 1024u)        // pinned (evict_last) prefix of x

// range policy: [x, x+PIN_BYTES) evict_last, [x+PIN_BYTES, x+X_BYTES) evict_first
__device__ __forceinline__ uint64_t mk_range_policy(const float* xbase) {
    uint64_t pol;
    asm volatile(
        "createpolicy.range.global.L2::evict_last.L2::evict_first.b64 %0, [%1], %2, %3;"
        : "=l"(pol)
        : "l"(xbase), "r"(PIN_BYTES), "r"(X_BYTES));
    return pol;
}

// float4 global load, non-coherent, with L2 cache-hint policy
__device__ __forceinline__ float4 ldg_pol(const float* p, uint64_t pol) {
    float4 v;
    asm volatile("ld.global.nc.L2::cache_hint.v4.f32 {%0,%1,%2,%3}, [%4], %5;"
                 : "=f"(v.x), "=f"(v.y), "=f"(v.z), "=f"(v.w)
                 : "l"(p), "l"(pol));
    return v;
}

__global__ __launch_bounds__(NTHREADS, 12)
void ssl2d_kernel(const float* __restrict__ x,
                  const float* __restrict__ a,
                  const float* __restrict__ b,
                  float* __restrict__ out) {
    const int plane = blockIdx.x;           // n * C + c
    const int c = plane - (plane / SSL_C) * SSL_C;

    const float av = __ldg(a + c);
    const float bv = __ldg(b + c);
    const float iaf = floorf(av);
    const float ibf = floorf(bv);
    const float fa = av - iaf;
    const float fb = bv - ibf;
    const int ia = (int)iaf;
    const int ib = (int)ibf;

    const float* __restrict__ xp = x + (size_t)plane * (SSL_H * SSL_W);
    float* __restrict__ op       = out + (size_t)plane * (SSL_H * SSL_W);

    const int tid = threadIdx.x;
    const int j = tid & 15;                 // lane within rowgroup (14,15 idle)
    const int rg = tid >> 4;                // rowgroup 0..7
    const int hbase = rg * ROWS_PT;         // first output row of this thread
    const int w = j << 2;
    const bool active = (j < 14);

    if (ia >= -1 && ia <= 0 && ib >= -1 && ib <= 0) {
        const uint64_t pol = mk_range_policy(x);

        // ---- fast path: 8 source-row LDG.128 issued up-front ----
        float4 q[ROWS_PT + 1];
        #pragma unroll
        for (int k = 0; k <= ROWS_PT; k++) {
            const int s = hbase + ia + k;
            q[k] = make_float4(0.f, 0.f, 0.f, 0.f);
            if (active & (s >= 0) & (s < SSL_H))
                q[k] = ldg_pol(xp + s * SSL_W + w, pol);
        }

        const float fb1 = 1.0f - fb;
        const float fa1 = 1.0f - fa;

        // rolling horizontal blend + vertical blend + store
        float4 Hp;                           // H[k-1]
        #pragma unroll
        for (int k = 0; k <= ROWS_PT; k++) {
            float4 Hc;
            if (ib == 0) {
                float e = __shfl_down_sync(0xffffffffu, q[k].x, 1); // col w+4
                if (j >= 13) e = 0.f;                               // w+4 >= 56
                Hc.x = fb1 * q[k].x + fb * q[k].y;
                Hc.y = fb1 * q[k].y + fb * q[k].z;
                Hc.z = fb1 * q[k].z + fb * q[k].w;
                Hc.w = fb1 * q[k].w + fb * e;
            } else {
                float e = __shfl_up_sync(0xffffffffu, q[k].w, 1);   // col w-1
                if (j == 0) e = 0.f;                                // w-1 < 0
                Hc.x = fb1 * e      + fb * q[k].x;
                Hc.y = fb1 * q[k].x + fb * q[k].y;
                Hc.z = fb1 * q[k].y + fb * q[k].z;
                Hc.w = fb1 * q[k].z + fb * q[k].w;
            }

            if (k > 0 && active) {
                float4 o;
                o.x = fa1 * Hp.x + fa * Hc.x;
                o.y = fa1 * Hp.y + fa * Hc.y;
                o.z = fa1 * Hp.z + fa * Hc.z;
                o.w = fa1 * Hp.w + fa * Hc.w;
                __stcs(reinterpret_cast<float4*>(op + (hbase + k - 1) * SSL_W + w), o);
            }
            Hp = Hc;
        }
    } else if (active) {
        // ---- generic fallback (shifts outside [-1,0]): predicated scalar LDG ----
        const float w00 = (1.0f - fa) * (1.0f - fb);
        const float w01 = (1.0f - fa) * fb;
        const float w10 = fa * (1.0f - fb);
        const float w11 = fa * fb;

        #pragma unroll
        for (int r = 0; r < ROWS_PT; r++) {
            const int h = hbase + r;
            const int h0 = h + ia;
            const int h1 = h0 + 1;
            const bool vh0 = (h0 >= 0) & (h0 < SSL_H);
            const bool vh1 = (h1 >= 0) & (h1 < SSL_H);
            const int wbase = w + ib;
            const float* row0 = xp + h0 * SSL_W;
            const float* row1 = xp + h1 * SSL_W;

            float r0[5], r1[5];
            #pragma unroll
            for (int i = 0; i < 5; i++) {
                const int ws = wbase + i;
                const bool vw = (ws >= 0) & (ws < SSL_W);
                r0[i] = (vh0 & vw) ? __ldg(row0 + ws) : 0.0f;
                r1[i] = (vh1 & vw) ? __ldg(row1 + ws) : 0.0f;
            }

            float4 o;
            o.x = w00 * r0[0] + w01 * r0[1] + w10 * r1[0] + w11 * r1[1];
            o.y = w00 * r0[1] + w01 * r0[2] + w10 * r1[1] + w11 * r1[2];
            o.z = w00 * r0[2] + w01 * r0[3] + w10 * r1[2] + w11 * r1[3];
            o.w = w00 * r0[3] + w01 * r0[4] + w10 * r1[3] + w11 * r1[4];
            __stcs(reinterpret_cast<float4*>(op + h * SSL_W + w), o);
        }
    }
}

extern "C" void kernel_launch(void* const* d_in, const int* in_sizes, int n_in,
                              void* d_out, int out_size) {
    const float* x = (const float*)d_in[0];
    const float* a = (const float*)d_in[1];
    const float* b = (const float*)d_in[2];
    float* out = (float*)d_out;

    const int B = 32;
    const int planes = B * SSL_C;           // 12288
    ssl2d_kernel<<<planes, NTHREADS>>>(x, a, b, out);
}

// round 17
// speedup vs baseline: 1.0069x; 1.0069x over previous
#include <cuda_runtime.h>
#include <cuda_bf16.h>
#include <cstdint>

// SSL2d: per-channel sub-pixel bilinear shift with zero padding.
// x: [B=32, C=384, H=56, W=56] fp32, a,b: [C] fp32.
//
// FINAL (= R13, the empirical best at 49.6us / 5.8TB/s):
//  - one CTA per (n,c) plane, grid 12288, block 128 = 8 rowgroups x 16 lanes
//  - 7 output rows per thread: 8 source-row LDG.128 issued up-front (MLP=8)
//  - rolling horizontal blend; warp shuffle supplies the single boundary
//    column per source row (seam/edge cases forced-zero)
//  - __stcs streaming stores (output never re-read)
//  - generic predicated-LDG fallback for shifts outside [-1,0]
// Falsified alternatives: smem staging (R2, -44%), persistent kernels
// (R7/R12, -12/-16%), L2 evict_last / range policies (R15/R16, 0/-8%).

#define SSL_H 56
#define SSL_W 56
#define SSL_C 384
#define ROWS_PT 7                           // output rows per thread
#define NRG (SSL_H / ROWS_PT)               // 8 rowgroups
#define NTHREADS (NRG * 16)                 // 128

__global__ __launch_bounds__(NTHREADS, 12)
void ssl2d_kernel(const float* __restrict__ x,
                  const float* __restrict__ a,
                  const float* __restrict__ b,
                  float* __restrict__ out) {
    const int plane = blockIdx.x;           // n * C + c
    const int c = plane - (plane / SSL_C) * SSL_C;

    const float av = __ldg(a + c);
    const float bv = __ldg(b + c);
    const float iaf = floorf(av);
    const float ibf = floorf(bv);
    const float fa = av - iaf;
    const float fb = bv - ibf;
    const int ia = (int)iaf;
    const int ib = (int)ibf;

    const float* __restrict__ xp = x + (size_t)plane * (SSL_H * SSL_W);
    float* __restrict__ op       = out + (size_t)plane * (SSL_H * SSL_W);

    const int tid = threadIdx.x;
    const int j = tid & 15;                 // lane within rowgroup (14,15 idle)
    const int rg = tid >> 4;                // rowgroup 0..7
    const int hbase = rg * ROWS_PT;         // first output row of this thread
    const int w = j << 2;
    const bool active = (j < 14);

    if (ia >= -1 && ia <= 0 && ib >= -1 && ib <= 0) {
        // ---- fast path: 8 source-row LDG.128 issued up-front ----
        float4 q[ROWS_PT + 1];
        #pragma unroll
        for (int k = 0; k <= ROWS_PT; k++) {
            const int s = hbase + ia + k;
            q[k] = make_float4(0.f, 0.f, 0.f, 0.f);
            if (active & (s >= 0) & (s < SSL_H))
                q[k] = *reinterpret_cast<const float4*>(xp + s * SSL_W + w);
        }

        const float fb1 = 1.0f - fb;
        const float fa1 = 1.0f - fa;

        // rolling horizontal blend + vertical blend + store
        float4 Hp;                           // H[k-1]
        #pragma unroll
        for (int k = 0; k <= ROWS_PT; k++) {
            float4 Hc;
            if (ib == 0) {
                float e = __shfl_down_sync(0xffffffffu, q[k].x, 1); // col w+4
                if (j >= 13) e = 0.f;                               // w+4 >= 56
                Hc.x = fb1 * q[k].x + fb * q[k].y;
                Hc.y = fb1 * q[k].y + fb * q[k].z;
                Hc.z = fb1 * q[k].z + fb * q[k].w;
                Hc.w = fb1 * q[k].w + fb * e;
            } else {
                float e = __shfl_up_sync(0xffffffffu, q[k].w, 1);   // col w-1
                if (j == 0) e = 0.f;                                // w-1 < 0
                Hc.x = fb1 * e      + fb * q[k].x;
                Hc.y = fb1 * q[k].x + fb * q[k].y;
                Hc.z = fb1 * q[k].y + fb * q[k].z;
                Hc.w = fb1 * q[k].z + fb * q[k].w;
            }

            if (k > 0 && active) {
                float4 o;
                o.x = fa1 * Hp.x + fa * Hc.x;
                o.y = fa1 * Hp.y + fa * Hc.y;
                o.z = fa1 * Hp.z + fa * Hc.z;
                o.w = fa1 * Hp.w + fa * Hc.w;
                __stcs(reinterpret_cast<float4*>(op + (hbase + k - 1) * SSL_W + w), o);
            }
            Hp = Hc;
        }
    } else if (active) {
        // ---- generic fallback (shifts outside [-1,0]): predicated scalar LDG ----
        const float w00 = (1.0f - fa) * (1.0f - fb);
        const float w01 = (1.0f - fa) * fb;
        const float w10 = fa * (1.0f - fb);
        const float w11 = fa * fb;

        #pragma unroll
        for (int r = 0; r < ROWS_PT; r++) {
            const int h = hbase + r;
            const int h0 = h + ia;
            const int h1 = h0 + 1;
            const bool vh0 = (h0 >= 0) & (h0 < SSL_H);
            const bool vh1 = (h1 >= 0) & (h1 < SSL_H);
            const int wbase = w + ib;
            const float* row0 = xp + h0 * SSL_W;
            const float* row1 = xp + h1 * SSL_W;

            float r0[5], r1[5];
            #pragma unroll
            for (int i = 0; i < 5; i++) {
                const int ws = wbase + i;
                const bool vw = (ws >= 0) & (ws < SSL_W);
                r0[i] = (vh0 & vw) ? __ldg(row0 + ws) : 0.0f;
                r1[i] = (vh1 & vw) ? __ldg(row1 + ws) : 0.0f;
            }

            float4 o;
            o.x = w00 * r0[0] + w01 * r0[1] + w10 * r1[0] + w11 * r1[1];
            o.y = w00 * r0[1] + w01 * r0[2] + w10 * r1[1] + w11 * r1[2];
            o.z = w00 * r0[2] + w01 * r0[3] + w10 * r1[2] + w11 * r1[3];
            o.w = w00 * r0[3] + w01 * r0[4] + w10 * r1[3] + w11 * r1[4];
            __stcs(reinterpret_cast<float4*>(op + h * SSL_W + w), o);
        }
    }
}

extern "C" void kernel_launch(void* const* d_in, const int* in_sizes, int n_in,
                              void* d_out, int out_size) {
    const float* x = (const float*)d_in[0];
    const float* a = (const float*)d_in[1];
    const float* b = (const float*)d_in[2];
    float* out = (float*)d_out;

    const int B = 32;
    const int planes = B * SSL_C;           // 12288
    ssl2d_kernel<<<planes, NTHREADS>>>(x, a, b, out);
}